// round 3
// baseline (speedup 1.0000x reference)
#include <cuda_runtime.h>
#include <cuda_bf16.h>

// y[b,n] = x[b,n] * W[n],  W[n] = sum over valid frames m of aw[j]*sw[j],
// j = (n mod 256) + 256*m, m in [max(0, q-8188), min(3, q)], q = n/256.
// Interior (3 <= q <= 8188): full 4-term sum, depends only on n mod 256.
//
// Kernel 1: branch-free stream, applies INTERIOR weights everywhere.
// Kernel 2: fixup, overwrites the 1536 boundary samples per row with the
//           truncated-sum weights.

#define HOPC      256u
#define NSAMP     (1u << 21)          // samples per row
#define NROWS     16u
#define QMAXV     8188u               // num_segments - 1
#define N4ROW     (NSAMP / 4u)        // float4 per row
#define TOTAL4    (NROWS * N4ROW)     // 8,388,608 float4
#define NBLK      4096u
#define NTHR      256u
#define PER_THREAD 8u                 // TOTAL4 / (NBLK*NTHR) exactly

// Boundary: q in {0,1,2} -> f4 [0,192), q in {8189..8191} -> last 192 f4.
#define BND4_LO   192u
#define BND4_HI   192u
#define BND4_ROW  (BND4_LO + BND4_HI) // 384
#define BND4_TOT  (NROWS * BND4_ROW)  // 6144

__global__ void __launch_bounds__(NTHR)
segmenter_stream_kernel(const float4* __restrict__ x,
                        const float*  __restrict__ aw,
                        const float*  __restrict__ sw,
                        float4*       __restrict__ y) {
    const unsigned tid = threadIdx.x;
    // Lane phase r = (4*tid) mod 256 — invariant across iterations because
    // the stride (NBLK*NTHR*4 samples) is a multiple of 256.
    const unsigned r = (tid << 2) & (HOPC - 1u);

    float w0 = 0.f, w1 = 0.f, w2 = 0.f, w3 = 0.f;
#pragma unroll
    for (int m = 0; m < 4; ++m) {
        const unsigned j = r + (unsigned)m * HOPC;
        w0 += aw[j + 0] * sw[j + 0];
        w1 += aw[j + 1] * sw[j + 1];
        w2 += aw[j + 2] * sw[j + 2];
        w3 += aw[j + 3] * sw[j + 3];
    }

    const unsigned base = blockIdx.x * NTHR + tid;

    // Front-batch all 8 loads (compile-time immediate offsets).
    float4 v[PER_THREAD];
#pragma unroll
    for (unsigned k = 0; k < PER_THREAD; ++k)
        v[k] = __ldcs(&x[base + k * (NBLK * NTHR)]);

#pragma unroll
    for (unsigned k = 0; k < PER_THREAD; ++k) {
        float4 t = v[k];
        t.x *= w0; t.y *= w1; t.z *= w2; t.w *= w3;
        __stcs(&y[base + k * (NBLK * NTHR)], t);
    }
}

__global__ void __launch_bounds__(NTHR)
segmenter_fixup_kernel(const float4* __restrict__ x,
                       const float*  __restrict__ aw,
                       const float*  __restrict__ sw,
                       float4*       __restrict__ y) {
    const unsigned idx = blockIdx.x * NTHR + threadIdx.x;
    if (idx >= BND4_TOT) return;

    const unsigned row    = idx / BND4_ROW;
    const unsigned within = idx % BND4_ROW;
    const unsigned f4 = (within < BND4_LO)
                          ? within
                          : (N4ROW - BND4_HI) + (within - BND4_LO);

    const unsigned n = f4 << 2;            // sample index within row
    const unsigned q = n >> 8;
    const unsigned r = n & (HOPC - 1u);

    const int m_lo = (q > QMAXV) ? (int)(q - QMAXV) : 0;
    const int m_hi = (q < 3u) ? (int)q : 3;

    float a0 = 0.f, a1 = 0.f, a2 = 0.f, a3 = 0.f;
    for (int m = m_lo; m <= m_hi; ++m) {
        const unsigned j = r + (unsigned)m * HOPC;
        a0 += aw[j + 0] * sw[j + 0];
        a1 += aw[j + 1] * sw[j + 1];
        a2 += aw[j + 2] * sw[j + 2];
        a3 += aw[j + 3] * sw[j + 3];
    }

    const unsigned i = row * N4ROW + f4;
    float4 t = x[i];
    t.x *= a0; t.y *= a1; t.z *= a2; t.w *= a3;
    y[i] = t;
}

extern "C" void kernel_launch(void* const* d_in, const int* in_sizes, int n_in,
                              void* d_out, int out_size) {
    const float4* x  = (const float4*)d_in[0];
    const float*  aw = (const float*)d_in[1];
    const float*  sw = (const float*)d_in[2];
    float4*       y  = (float4*)d_out;

    (void)in_sizes; (void)n_in; (void)out_size;

    segmenter_stream_kernel<<<NBLK, NTHR>>>(x, aw, sw, y);
    segmenter_fixup_kernel<<<(BND4_TOT + NTHR - 1) / NTHR, NTHR>>>(x, aw, sw, y);
}

// round 4
// speedup vs baseline: 1.0442x; 1.0442x over previous
#include <cuda_runtime.h>
#include <cuda_bf16.h>

// y[b,n] = x[b,n] * W[n],  W[n] = sum over valid frames m of aw[j]*sw[j],
// j = (n mod 256) + 256*m, m in [max(0, q-8188), min(3, q)], q = n/256.
//
// Key structural fact: the grid stride (NBLK*NTHR float4 = 4,194,304 samples)
// is an exact multiple of NSAMP (2,097,152), so n = (4*i) mod NSAMP is the
// SAME for all 8 iterations of a thread. W (including boundary truncation)
// is a per-thread constant -> compute once, hot loop is branch-free.

#define HOPC      256u
#define NSAMP     (1u << 21)          // samples per row
#define NROWS     16u
#define QMAXV     8188u               // num_segments - 1
#define TOTAL4    ((NROWS * NSAMP) / 4u)   // 8,388,608 float4
#define NBLK      4096u
#define NTHR      256u
#define PER_THREAD 8u                 // TOTAL4 / (NBLK*NTHR) exactly

__global__ void __launch_bounds__(NTHR)
segmenter_roundtrip_kernel(const float4* __restrict__ x,
                           const float*  __restrict__ aw,
                           const float*  __restrict__ sw,
                           float4*       __restrict__ y) {
    const unsigned tid  = threadIdx.x;
    const unsigned base = blockIdx.x * NTHR + tid;

    // Per-thread sample phase (k-invariant: stride*4 ≡ 0 mod NSAMP).
    const unsigned n = (base << 2) & (NSAMP - 1u);
    const unsigned q = n >> 8;
    const unsigned r = n & (HOPC - 1u);

    // Truncated frame range (interior: [0,3]).
    const int m_lo = (q > QMAXV) ? (int)(q - QMAXV) : 0;
    const int m_hi = (q < 3u) ? (int)q : 3;

    // Per-thread weights, predicated accumulation (branch-free prologue;
    // windows are tiny and L1/L2-hot).
    float w0 = 0.f, w1 = 0.f, w2 = 0.f, w3 = 0.f;
#pragma unroll
    for (int m = 0; m < 4; ++m) {
        const float mask = (m >= m_lo && m <= m_hi) ? 1.0f : 0.0f;
        const unsigned j = r + (unsigned)m * HOPC;
        w0 += mask * aw[j + 0] * sw[j + 0];
        w1 += mask * aw[j + 1] * sw[j + 1];
        w2 += mask * aw[j + 2] * sw[j + 2];
        w3 += mask * aw[j + 3] * sw[j + 3];
    }

    // ---- Front-batch all 8 loads (MLP = 8, compile-time offsets) ----
    float4 v[PER_THREAD];
#pragma unroll
    for (unsigned k = 0; k < PER_THREAD; ++k)
        v[k] = __ldcs(&x[base + k * (NBLK * NTHR)]);

    // ---- Scale + store, branch-free ----
#pragma unroll
    for (unsigned k = 0; k < PER_THREAD; ++k) {
        float4 t = v[k];
        t.x *= w0; t.y *= w1; t.z *= w2; t.w *= w3;
        __stcs(&y[base + k * (NBLK * NTHR)], t);
    }
}

extern "C" void kernel_launch(void* const* d_in, const int* in_sizes, int n_in,
                              void* d_out, int out_size) {
    const float4* x  = (const float4*)d_in[0];
    const float*  aw = (const float*)d_in[1];
    const float*  sw = (const float*)d_in[2];
    float4*       y  = (float4*)d_out;

    (void)in_sizes; (void)n_in; (void)out_size;

    segmenter_roundtrip_kernel<<<NBLK, NTHR>>>(x, aw, sw, y);
}

// round 5
// speedup vs baseline: 1.0539x; 1.0092x over previous
#include <cuda_runtime.h>
#include <cuda_bf16.h>

// y[b,n] = x[b,n] * W[n],  W[n] = sum over valid frames m of aw[j]*sw[j],
// j = (n mod 256) + 256*m, m in [max(0, q-8188), min(3, q)], q = n/256.
//
// Launch geometry: 2048 blocks x 256 threads = 524,288 threads = exactly one
// row of float4s (N4ROW). Thread t owns float4 index `base` in EVERY row
// (k = 0..15). Its sample phase n = 4*base is fixed -> weights (incl.
// boundary truncation) are a per-thread constant computed once.

#define HOPC      256u
#define NSAMP     (1u << 21)          // samples per row
#define NROWS     16u
#define QMAXV     8188u               // num_segments - 1
#define N4ROW     (NSAMP / 4u)        // 524,288 float4 per row
#define NBLK      2048u
#define NTHR      256u

__global__ void __launch_bounds__(NTHR)
segmenter_roundtrip_kernel(const float4* __restrict__ x,
                           const float4* __restrict__ aw4,
                           const float4* __restrict__ sw4,
                           float4*       __restrict__ y) {
    const unsigned base = blockIdx.x * NTHR + threadIdx.x;  // f4 idx in row

    const unsigned n = base << 2;            // sample index within row
    const unsigned q = n >> 8;               // frame-phase index
    const unsigned r4 = (n & (HOPC - 1u)) >> 2;  // float4 index of r

    // Truncated frame range (interior: [0,3]).
    const int m_lo = (q > QMAXV) ? (int)(q - QMAXV) : 0;
    const int m_hi = (q < 3u) ? (int)q : 3;

    // Per-thread weights: 8 vector loads total (windows L1/L2-hot).
    float w0 = 0.f, w1 = 0.f, w2 = 0.f, w3 = 0.f;
#pragma unroll
    for (int m = 0; m < 4; ++m) {
        const float mask = (m >= m_lo && m <= m_hi) ? 1.0f : 0.0f;
        const float4 a = aw4[r4 + (unsigned)m * (HOPC / 4u)];
        const float4 s = sw4[r4 + (unsigned)m * (HOPC / 4u)];
        w0 += mask * a.x * s.x;
        w1 += mask * a.y * s.y;
        w2 += mask * a.z * s.z;
        w3 += mask * a.w * s.w;
    }

    // 16 rows, two batches of 8 (MLP=8 within a batch, 32 data regs).
#pragma unroll
    for (unsigned b = 0; b < 2; ++b) {
        float4 v[8];
#pragma unroll
        for (unsigned k = 0; k < 8; ++k)
            v[k] = __ldcg(&x[(b * 8u + k) * N4ROW + base]);
#pragma unroll
        for (unsigned k = 0; k < 8; ++k) {
            float4 t = v[k];
            t.x *= w0; t.y *= w1; t.z *= w2; t.w *= w3;
            __stcg(&y[(b * 8u + k) * N4ROW + base], t);
        }
    }
}

extern "C" void kernel_launch(void* const* d_in, const int* in_sizes, int n_in,
                              void* d_out, int out_size) {
    const float4* x  = (const float4*)d_in[0];
    const float4* aw = (const float4*)d_in[1];
    const float4* sw = (const float4*)d_in[2];
    float4*       y  = (float4*)d_out;

    (void)in_sizes; (void)n_in; (void)out_size;

    segmenter_roundtrip_kernel<<<NBLK, NTHR>>>(x, aw, sw, y);
}